// round 7
// baseline (speedup 1.0000x reference)
#include <cuda_runtime.h>
#include <cstdint>
#include <cstddef>

#define B_   128
#define T_   512
#define H_   256
#define G4_  1024

// recurrence cluster geometry
#define CLUS 8              // CTAs per cluster
#define RPC  8              // batch rows per cluster
#define JL   32             // h-columns per CTA
#define HROW 260            // padded h row stride (floats)
// smem layout: Us2 [256][32] ulonglong2 = 128KB | hsb [2][8][260] f32 | comb [256] ulonglong2
#define OFF_HS   131072
#define OFF_COMB (OFF_HS + 2*RPC*HROW*4)
#define REC_SMEM (OFF_COMB + 256*16)

// ---------------- scratch (device globals; no allocation allowed) ----------------
__device__ float g_xz[(size_t)B_ * T_ * G4_];    // gate pre-activations (reused per layer)
__device__ float g_hseq[(size_t)B_ * T_ * H_];   // per-layer hidden sequence (reused)

// ---------------- packed f32x2 helpers (sm_103a FFMA2) ----------------
static __device__ __forceinline__ unsigned long long f2pack(float a, float b) {
    unsigned long long r;
    asm("mov.b64 %0, {%1, %2};" : "=l"(r) : "r"(__float_as_uint(a)), "r"(__float_as_uint(b)));
    return r;
}
static __device__ __forceinline__ void f2unpack(unsigned long long v, float& a, float& b) {
    unsigned int x, y;
    asm("mov.b64 {%0, %1}, %2;" : "=r"(x), "=r"(y) : "l"(v));
    a = __uint_as_float(x); b = __uint_as_float(y);
}
static __device__ __forceinline__ unsigned long long f2fma(
    unsigned long long a, unsigned long long b, unsigned long long c) {
    unsigned long long d;
    asm("fma.rn.f32x2 %0, %1, %2, %3;" : "=l"(d) : "l"(a), "l"(b), "l"(c));
    return d;
}
static __device__ __forceinline__ unsigned long long f2add(
    unsigned long long a, unsigned long long b) {
    unsigned long long d;
    asm("add.rn.f32x2 %0, %1, %2;" : "=l"(d) : "l"(a), "l"(b));
    return d;
}

// fast activations (rel err ~1e-6; tolerance 1e-3)
static __device__ __forceinline__ float sig_f(float x) {
    return __fdividef(1.f, 1.f + __expf(-x));
}
static __device__ __forceinline__ float tanh_f(float x) {
    return __fdividef(2.f, 1.f + __expf(-2.f * x)) - 1.f;
}

// ---------------- DSMEM helpers ----------------
static __device__ __forceinline__ unsigned int smem_u32(const void* p) {
    return (unsigned int)__cvta_generic_to_shared(p);
}
static __device__ __forceinline__ void st_cluster_f32(unsigned int laddr, unsigned int rank, float v) {
    unsigned int ra;
    asm volatile("mapa.shared::cluster.u32 %0, %1, %2;" : "=r"(ra) : "r"(laddr), "r"(rank));
    asm volatile("st.shared::cluster.f32 [%0], %1;" :: "r"(ra), "f"(v) : "memory");
}
static __device__ __forceinline__ void st_local_f32(unsigned int laddr, float v) {
    asm volatile("st.shared.f32 [%0], %1;" :: "r"(laddr), "f"(v) : "memory");
}
#define CLUSTER_SYNC() do { \
    asm volatile("barrier.cluster.arrive.aligned;" ::: "memory"); \
    asm volatile("barrier.cluster.wait.aligned;" ::: "memory"); \
} while (0)

// ---------------- GEMM: C[M,N] = A[M,256] @ Bw[256,N] + bias (+tanh) ----------------
// BM=128, BN=128, BK=16, 256 threads, 8x8/thread, As pre-duplicated (a,a) u64.
template <bool TANH>
__global__ __launch_bounds__(256, 2) void gemm_bias(
    const float* __restrict__ A, const float* __restrict__ Bw,
    const float* __restrict__ bias, float* __restrict__ C, int N)
{
    __shared__ unsigned long long As2[16][130];
    __shared__ float Bs[16][132];
    const int tid = threadIdx.x;
    const int m0 = blockIdx.y * 128;
    const int n0 = blockIdx.x * 128;
    const int tr = tid >> 4;
    const int tc = tid & 15;

    unsigned long long acc[8][4];
#pragma unroll
    for (int i = 0; i < 8; i++)
#pragma unroll
        for (int p = 0; p < 4; p++) acc[i][p] = 0ULL;

    for (int k0 = 0; k0 < 256; k0 += 16) {
#pragma unroll
        for (int s = 0; s < 2; s++) {
            int e = tid + s * 256;
            int row = e >> 2, q = e & 3;
            float4 v = *(const float4*)&A[(size_t)(m0 + row) * 256 + k0 + q * 4];
            As2[q * 4 + 0][row] = f2pack(v.x, v.x);
            As2[q * 4 + 1][row] = f2pack(v.y, v.y);
            As2[q * 4 + 2][row] = f2pack(v.z, v.z);
            As2[q * 4 + 3][row] = f2pack(v.w, v.w);
        }
#pragma unroll
        for (int s = 0; s < 2; s++) {
            int e = tid + s * 256;
            int krow = e >> 5, nq = e & 31;
            *(float4*)&Bs[krow][nq * 4] =
                *(const float4*)&Bw[(size_t)(k0 + krow) * N + n0 + nq * 4];
        }
        __syncthreads();
#pragma unroll
        for (int kk = 0; kk < 16; kk++) {
            ulonglong2 a0 = *(const ulonglong2*)&As2[kk][tr * 8 + 0];
            ulonglong2 a1 = *(const ulonglong2*)&As2[kk][tr * 8 + 2];
            ulonglong2 a2 = *(const ulonglong2*)&As2[kk][tr * 8 + 4];
            ulonglong2 a3 = *(const ulonglong2*)&As2[kk][tr * 8 + 6];
            ulonglong2 b0 = *(const ulonglong2*)&Bs[kk][tc * 8 + 0];
            ulonglong2 b1 = *(const ulonglong2*)&Bs[kk][tc * 8 + 4];
            unsigned long long ap[8] = {a0.x, a0.y, a1.x, a1.y, a2.x, a2.y, a3.x, a3.y};
            unsigned long long bp[4] = {b0.x, b0.y, b1.x, b1.y};
#pragma unroll
            for (int i = 0; i < 8; i++)
#pragma unroll
                for (int p = 0; p < 4; p++)
                    acc[i][p] = f2fma(ap[i], bp[p], acc[i][p]);
        }
        __syncthreads();
    }

    float4 bv0 = *(const float4*)&bias[n0 + tc * 8];
    float4 bv1 = *(const float4*)&bias[n0 + tc * 8 + 4];
#pragma unroll
    for (int i = 0; i < 8; i++) {
        float c0, c1, c2, c3, c4, c5, c6, c7;
        f2unpack(acc[i][0], c0, c1);
        f2unpack(acc[i][1], c2, c3);
        f2unpack(acc[i][2], c4, c5);
        f2unpack(acc[i][3], c6, c7);
        c0 += bv0.x; c1 += bv0.y; c2 += bv0.z; c3 += bv0.w;
        c4 += bv1.x; c5 += bv1.y; c6 += bv1.z; c7 += bv1.w;
        if (TANH) {
            c0 = tanh_f(c0); c1 = tanh_f(c1); c2 = tanh_f(c2); c3 = tanh_f(c3);
            c4 = tanh_f(c4); c5 = tanh_f(c5); c6 = tanh_f(c6); c7 = tanh_f(c7);
        }
        float* cp = &C[(size_t)(m0 + tr * 8 + i) * N + n0 + tc * 8];
        *(float4*)cp = make_float4(c0, c1, c2, c3);
        *(float4*)(cp + 4) = make_float4(c4, c5, c6, c7);
    }
}

// ---------------- persistent LSTM recurrence (v4b: 8-CTA cluster + DSMEM) ----------------
// 16 clusters x 8 CTAs; clusters fully independent (no inter-cluster sync anywhere).
// Cluster = 8 batch rows, full H=256 (each CTA: 32 h-cols, U slice resident in smem).
// h exchanged via st.shared::cluster; one barrier.cluster per step.
__global__ __launch_bounds__(512) __cluster_dims__(CLUS, 1, 1)
void lstm_rec(const float* __restrict__ xz, const float* __restrict__ U,
              float* __restrict__ hseq)
{
    extern __shared__ unsigned char sraw[];
    ulonglong2* Us2 = (ulonglong2*)sraw;                 // [256 k][32 jl] (i,f)|(g,o)
    float* hsb = (float*)(sraw + OFF_HS);                // [2][RPC][HROW]
    ulonglong2* comb = (ulonglong2*)(sraw + OFF_COMB);   // [256] hi-half partials

    const int tid = threadIdx.x;
    unsigned int rank;
    asm("mov.u32 %0, %%cluster_ctarank;" : "=r"(rank));
    const int r0 = (blockIdx.x >> 3) * RPC;   // global batch row base of cluster
    const int jb = (int)rank * JL;            // global h-col base of this CTA
    const int kh = tid >> 8;                  // k-half
    const int lane = tid & 31;
    const int wl = (tid >> 5) & 7;            // warp-in-half
    const int r = lane >> 2;                  // 0..7
    const int jl = wl * 4 + (lane & 3);       // 0..31
    const int cell = jl * 8 + r;

    // Load U slice once: Us2[k*32+jl] = {(U[k][i],U[k][f]), (U[k][g],U[k][o])}
    for (int e = tid; e < 8192; e += 512) {
        int k = e >> 5, jj = e & 31;
        const float* up = U + (size_t)k * G4_ + jb + jj;
        ulonglong2 v;
        v.x = f2pack(up[0], up[256]);
        v.y = f2pack(up[512], up[768]);
        Us2[e] = v;
    }
    // Zero both h buffers
    for (int e = tid; e < 2 * RPC * HROW; e += 512) hsb[e] = 0.f;
    __syncthreads();
    CLUSTER_SYNC();   // peers' h buffers zeroed before any DSMEM stores land

    const unsigned int hsb_u32 = smem_u32(hsb);
    float c = 0.f;

    // Prime xz pipeline for t=0 (low-half threads carry the gate bias terms)
    float cz0 = 0.f, cz1 = 0.f, cz2 = 0.f, cz3 = 0.f;
    if (kh == 0) {
        const float* xp = xz + (size_t)(r0 + r) * T_ * G4_ + jb + jl;
        cz0 = __ldcs(xp);
        cz1 = __ldcs(xp + 256);
        cz2 = __ldcs(xp + 512);
        cz3 = __ldcs(xp + 768);
    }

    for (int t = 0; t < T_; ++t) {
        const float* hrow = hsb + (t & 1) * (RPC * HROW) + r * HROW + kh * 128;
        const ulonglong2* up = Us2 + (size_t)(kh * 128) * JL + jl;

        // Prefetch next step's gate pre-activations (hidden behind FMA loop)
        float nz0 = 0.f, nz1 = 0.f, nz2 = 0.f, nz3 = 0.f;
        if (kh == 0) {
            int tn = (t + 1 < T_) ? t + 1 : t;
            const float* xp = xz + ((size_t)(r0 + r) * T_ + tn) * G4_ + jb + jl;
            nz0 = __ldcs(xp);
            nz1 = __ldcs(xp + 256);
            nz2 = __ldcs(xp + 512);
            nz3 = __ldcs(xp + 768);
        }

        unsigned long long accA = (kh == 0) ? f2pack(cz0, cz1) : 0ULL;
        unsigned long long accB = (kh == 0) ? f2pack(cz2, cz3) : 0ULL;
#pragma unroll 8
        for (int k4 = 0; k4 < 32; k4++) {
            float4 h4 = *(const float4*)&hrow[k4 * 4];
            {
                unsigned long long hh = f2pack(h4.x, h4.x);
                ulonglong2 u = up[(size_t)(k4 * 4 + 0) * JL];
                accA = f2fma(hh, u.x, accA); accB = f2fma(hh, u.y, accB);
            }
            {
                unsigned long long hh = f2pack(h4.y, h4.y);
                ulonglong2 u = up[(size_t)(k4 * 4 + 1) * JL];
                accA = f2fma(hh, u.x, accA); accB = f2fma(hh, u.y, accB);
            }
            {
                unsigned long long hh = f2pack(h4.z, h4.z);
                ulonglong2 u = up[(size_t)(k4 * 4 + 2) * JL];
                accA = f2fma(hh, u.x, accA); accB = f2fma(hh, u.y, accB);
            }
            {
                unsigned long long hh = f2pack(h4.w, h4.w);
                ulonglong2 u = up[(size_t)(k4 * 4 + 3) * JL];
                accA = f2fma(hh, u.x, accA); accB = f2fma(hh, u.y, accB);
            }
        }
        if (kh == 1) comb[cell] = make_ulonglong2(accA, accB);
        __syncthreads();

        if (kh == 0) {
            ulonglong2 p = comb[cell];
            accA = f2add(accA, p.x);
            accB = f2add(accB, p.y);
            float azi, azf, azg, azo;
            f2unpack(accA, azi, azf);
            f2unpack(accB, azg, azo);
            float ig = sig_f(azi);
            float fg = sig_f(azf);
            float gg = tanh_f(azg);
            float og = sig_f(azo);
            c = fg * c + ig * gg;
            float h = og * tanh_f(c);
            __stcs(&hseq[((size_t)(r0 + r) * T_ + t) * H_ + jb + jl], h);
            // Broadcast h into every cluster CTA's next-step h buffer
            unsigned int la = hsb_u32
                + (unsigned int)(((t + 1) & 1) * (RPC * HROW) + r * HROW + jb + jl) * 4u;
            st_local_f32(la, h);   // own copy via plain st.shared
#pragma unroll
            for (unsigned int p8 = 0; p8 < CLUS; p8++) {
                if (p8 != rank) st_cluster_f32(la, p8, h);
            }
        }
        cz0 = nz0; cz1 = nz1; cz2 = nz2; cz3 = nz3;
        CLUSTER_SYNC();   // h(t+1) visible cluster-wide
    }
}

// ---------------- LayerNorm over last dim (256), one warp per row ----------------
__global__ __launch_bounds__(256) void ln_kernel(
    const float* __restrict__ X, const float* __restrict__ gamma,
    const float* __restrict__ beta, float* __restrict__ out)
{
    int w = threadIdx.x >> 5, lane = threadIdx.x & 31;
    size_t row = (size_t)blockIdx.x * 8 + w;
    const float* x = X + row * 256;
    float4 v0 = *(const float4*)&x[lane * 4];
    float4 v1 = *(const float4*)&x[128 + lane * 4];
    float s = v0.x + v0.y + v0.z + v0.w + v1.x + v1.y + v1.z + v1.w;
    float q = v0.x * v0.x + v0.y * v0.y + v0.z * v0.z + v0.w * v0.w
            + v1.x * v1.x + v1.y * v1.y + v1.z * v1.z + v1.w * v1.w;
#pragma unroll
    for (int o = 16; o > 0; o >>= 1) {
        s += __shfl_xor_sync(0xFFFFFFFFu, s, o);
        q += __shfl_xor_sync(0xFFFFFFFFu, q, o);
    }
    float mu = s * (1.f / 256.f);
    float var = q * (1.f / 256.f) - mu * mu;
    float rstd = rsqrtf(var + 1e-3f);
    float4 g0 = *(const float4*)&gamma[lane * 4];
    float4 g1 = *(const float4*)&gamma[128 + lane * 4];
    float4 e0 = *(const float4*)&beta[lane * 4];
    float4 e1 = *(const float4*)&beta[128 + lane * 4];
    float4 o0, o1;
    o0.x = (v0.x - mu) * rstd * g0.x + e0.x;
    o0.y = (v0.y - mu) * rstd * g0.y + e0.y;
    o0.z = (v0.z - mu) * rstd * g0.z + e0.z;
    o0.w = (v0.w - mu) * rstd * g0.w + e0.w;
    o1.x = (v1.x - mu) * rstd * g1.x + e1.x;
    o1.y = (v1.y - mu) * rstd * g1.y + e1.y;
    o1.z = (v1.z - mu) * rstd * g1.z + e1.z;
    o1.w = (v1.w - mu) * rstd * g1.w + e1.w;
    float* op = out + row * 256;
    *(float4*)&op[lane * 4] = o0;
    *(float4*)&op[128 + lane * 4] = o1;
}

// ---------------- entry point ----------------
extern "C" void kernel_launch(void* const* d_in, const int* in_sizes, int n_in,
                              void* d_out, int out_size)
{
    const float* x  = (const float*)d_in[0];
    const float* W0 = (const float*)d_in[1];
    const float* U0 = (const float*)d_in[2];
    const float* b0 = (const float*)d_in[3];
    const float* W1 = (const float*)d_in[4];
    const float* U1 = (const float*)d_in[5];
    const float* b1 = (const float*)d_in[6];
    const float* Wd = (const float*)d_in[7];
    const float* bd = (const float*)d_in[8];
    const float* ga = (const float*)d_in[9];
    const float* be = (const float*)d_in[10];
    float* out = (float*)d_out;

    float *xz, *hseq;
    cudaGetSymbolAddress((void**)&xz, g_xz);
    cudaGetSymbolAddress((void**)&hseq, g_hseq);
    cudaFuncSetAttribute(lstm_rec, cudaFuncAttributeMaxDynamicSharedMemorySize, REC_SMEM);

    // Layer 0
    gemm_bias<false><<<dim3(8, 512), 256>>>(x, W0, b0, xz, G4_);
    lstm_rec<<<128, 512, REC_SMEM>>>(xz, U0, hseq);
    // Layer 1
    gemm_bias<false><<<dim3(8, 512), 256>>>(hseq, W1, b1, xz, G4_);
    lstm_rec<<<128, 512, REC_SMEM>>>(xz, U1, hseq);
    // Dense + tanh (into g_xz scratch), then LayerNorm
    gemm_bias<true><<<dim3(2, 512), 256>>>(hseq, Wd, bd, xz, H_);
    ln_kernel<<<8192, 256>>>(xz, ga, be, out);
}

// round 8
// speedup vs baseline: 1.5984x; 1.5984x over previous
#include <cuda_runtime.h>
#include <cstdint>
#include <cstddef>

#define B_   128
#define T_   512
#define H_   256
#define G4_  1024

// recurrence geometry: 16 independent row-groups x 16 CTAs, 8 rows/group
#define NGRP2    16
#define GRP_CTAS 16
#define RPC2     8
#define JL2      16
#define HROW     260
// smem: Us2 [256 k][16 j] ulonglong2 = 64KB | hs [8][260] f32 | comb [128] ulonglong2
#define OFF_HS   65536
#define OFF_COMB (OFF_HS + RPC2*HROW*4)
#define REC_SMEM (OFF_COMB + 128*16)

// ---------------- scratch (device globals; no allocation allowed) ----------------
__device__ float g_xz[(size_t)B_ * T_ * G4_];    // gate pre-activations (reused per layer)
__device__ float g_hseq[(size_t)B_ * T_ * H_];   // per-layer hidden sequence (also h-exchange)
__device__ unsigned long long g_arrive[NGRP2 * 16];   // padded per-group counters
__device__ unsigned long long g_release[NGRP2 * 16];

// ---------------- packed f32x2 helpers (sm_103a FFMA2) ----------------
static __device__ __forceinline__ unsigned long long f2pack(float a, float b) {
    unsigned long long r;
    asm("mov.b64 %0, {%1, %2};" : "=l"(r) : "r"(__float_as_uint(a)), "r"(__float_as_uint(b)));
    return r;
}
static __device__ __forceinline__ void f2unpack(unsigned long long v, float& a, float& b) {
    unsigned int x, y;
    asm("mov.b64 {%0, %1}, %2;" : "=r"(x), "=r"(y) : "l"(v));
    a = __uint_as_float(x); b = __uint_as_float(y);
}
static __device__ __forceinline__ unsigned long long f2fma(
    unsigned long long a, unsigned long long b, unsigned long long c) {
    unsigned long long d;
    asm("fma.rn.f32x2 %0, %1, %2, %3;" : "=l"(d) : "l"(a), "l"(b), "l"(c));
    return d;
}
static __device__ __forceinline__ unsigned long long f2add(
    unsigned long long a, unsigned long long b) {
    unsigned long long d;
    asm("add.rn.f32x2 %0, %1, %2;" : "=l"(d) : "l"(a), "l"(b));
    return d;
}

// fast activations (rel err ~1e-6; tolerance 1e-3)
static __device__ __forceinline__ float sig_f(float x) {
    return __fdividef(1.f, 1.f + __expf(-x));
}
static __device__ __forceinline__ float tanh_f(float x) {
    return __fdividef(2.f, 1.f + __expf(-2.f * x)) - 1.f;
}

// ---------------- per-row-group barrier (16 CTAs, groups independent) ----------------
static __device__ __forceinline__ void gsync(int grp, unsigned long long& phase) {
    __threadfence();     // every thread publishes its own stores before arrival
    __syncthreads();
    if (threadIdx.x == 0) {
        unsigned long long old = atomicAdd(&g_arrive[grp * 16], 1ULL);
        if (old == phase * GRP_CTAS + (GRP_CTAS - 1)) {
            __threadfence();
            *(volatile unsigned long long*)&g_release[grp * 16] = phase + 1;
        } else {
            while (*(volatile unsigned long long*)&g_release[grp * 16] <= phase) { }
        }
        phase++;
    }
    __syncthreads();
}

// ---------------- GEMM: C[M,N] = A[M,256] @ Bw[256,N] + bias (+tanh) ----------------
// BM=128, BN=128, BK=16, 256 threads, 8x8/thread, As pre-duplicated (a,a) u64.
template <bool TANH>
__global__ __launch_bounds__(256, 2) void gemm_bias(
    const float* __restrict__ A, const float* __restrict__ Bw,
    const float* __restrict__ bias, float* __restrict__ C, int N)
{
    __shared__ unsigned long long As2[16][130];
    __shared__ float Bs[16][132];
    const int tid = threadIdx.x;
    const int m0 = blockIdx.y * 128;
    const int n0 = blockIdx.x * 128;
    const int tr = tid >> 4;
    const int tc = tid & 15;

    unsigned long long acc[8][4];
#pragma unroll
    for (int i = 0; i < 8; i++)
#pragma unroll
        for (int p = 0; p < 4; p++) acc[i][p] = 0ULL;

    for (int k0 = 0; k0 < 256; k0 += 16) {
#pragma unroll
        for (int s = 0; s < 2; s++) {
            int e = tid + s * 256;
            int row = e >> 2, q = e & 3;
            float4 v = *(const float4*)&A[(size_t)(m0 + row) * 256 + k0 + q * 4];
            As2[q * 4 + 0][row] = f2pack(v.x, v.x);
            As2[q * 4 + 1][row] = f2pack(v.y, v.y);
            As2[q * 4 + 2][row] = f2pack(v.z, v.z);
            As2[q * 4 + 3][row] = f2pack(v.w, v.w);
        }
#pragma unroll
        for (int s = 0; s < 2; s++) {
            int e = tid + s * 256;
            int krow = e >> 5, nq = e & 31;
            *(float4*)&Bs[krow][nq * 4] =
                *(const float4*)&Bw[(size_t)(k0 + krow) * N + n0 + nq * 4];
        }
        __syncthreads();
#pragma unroll
        for (int kk = 0; kk < 16; kk++) {
            ulonglong2 a0 = *(const ulonglong2*)&As2[kk][tr * 8 + 0];
            ulonglong2 a1 = *(const ulonglong2*)&As2[kk][tr * 8 + 2];
            ulonglong2 a2 = *(const ulonglong2*)&As2[kk][tr * 8 + 4];
            ulonglong2 a3 = *(const ulonglong2*)&As2[kk][tr * 8 + 6];
            ulonglong2 b0 = *(const ulonglong2*)&Bs[kk][tc * 8 + 0];
            ulonglong2 b1 = *(const ulonglong2*)&Bs[kk][tc * 8 + 4];
            unsigned long long ap[8] = {a0.x, a0.y, a1.x, a1.y, a2.x, a2.y, a3.x, a3.y};
            unsigned long long bp[4] = {b0.x, b0.y, b1.x, b1.y};
#pragma unroll
            for (int i = 0; i < 8; i++)
#pragma unroll
                for (int p = 0; p < 4; p++)
                    acc[i][p] = f2fma(ap[i], bp[p], acc[i][p]);
        }
        __syncthreads();
    }

    float4 bv0 = *(const float4*)&bias[n0 + tc * 8];
    float4 bv1 = *(const float4*)&bias[n0 + tc * 8 + 4];
#pragma unroll
    for (int i = 0; i < 8; i++) {
        float c0, c1, c2, c3, c4, c5, c6, c7;
        f2unpack(acc[i][0], c0, c1);
        f2unpack(acc[i][1], c2, c3);
        f2unpack(acc[i][2], c4, c5);
        f2unpack(acc[i][3], c6, c7);
        c0 += bv0.x; c1 += bv0.y; c2 += bv0.z; c3 += bv0.w;
        c4 += bv1.x; c5 += bv1.y; c6 += bv1.z; c7 += bv1.w;
        if (TANH) {
            c0 = tanh_f(c0); c1 = tanh_f(c1); c2 = tanh_f(c2); c3 = tanh_f(c3);
            c4 = tanh_f(c4); c5 = tanh_f(c5); c6 = tanh_f(c6); c7 = tanh_f(c7);
        }
        float* cp = &C[(size_t)(m0 + tr * 8 + i) * N + n0 + tc * 8];
        *(float4*)cp = make_float4(c0, c1, c2, c3);
        *(float4*)(cp + 4) = make_float4(c4, c5, c6, c7);
    }
}

// ---------------- persistent LSTM recurrence (v5: 16 groups x 16 CTAs, 2-3/SM) ----------------
// 256 CTAs; group = 8 batch rows. Co-resident CTAs from DIFFERENT groups hide each
// other's serial-region latency. h exchanged directly through L2-hot hseq[t-1].
__global__ __launch_bounds__(256, 2) void lstm_rec(
    const float* __restrict__ xz, const float* __restrict__ U, float* __restrict__ hseq)
{
    extern __shared__ unsigned char sraw[];
    ulonglong2* Us2 = (ulonglong2*)sraw;                       // [256 k][16 j]
    float* hs = (float*)(sraw + OFF_HS);                       // [8][260]
    ulonglong2* comb = (ulonglong2*)(sraw + OFF_COMB);         // [128]

    const int tid = threadIdx.x;
    const int cta = blockIdx.x;
    const int grp = cta >> 4;            // 0..15
    const int r0 = grp * RPC2;           // batch rows
    const int j0 = (cta & 15) * JL2;     // h columns
    const int w = tid >> 5;
    const int lane = tid & 31;
    const int kh = w >> 2;               // k-half
    const int r = lane >> 2;             // 0..7
    const int j = (w & 3) * 4 + (lane & 3);  // 0..15
    const int cell = j * 8 + r;          // 0..127

    // Load U slice once: Us2[k*16+j] = {(U[k][i],U[k][f]), (U[k][g],U[k][o])}
    for (int e = tid; e < 4096; e += 256) {
        int k = e >> 4, jj = e & 15;
        const float* up = U + (size_t)k * G4_ + j0 + jj;
        ulonglong2 v;
        v.x = f2pack(up[0], up[256]);
        v.y = f2pack(up[512], up[768]);
        Us2[e] = v;
    }
    // Zero h tile (used as h(-1) = 0 at t=0)
    for (int e = tid; e < RPC2 * HROW; e += 256) hs[e] = 0.f;

    float c = 0.f;
    unsigned long long phase = 0;
    if (tid == 0) phase = *(volatile unsigned long long*)&g_release[grp * 16];

    // Prime xz pipeline for t=0 (kh==0 threads own the cells)
    float cz0 = 0.f, cz1 = 0.f, cz2 = 0.f, cz3 = 0.f;
    if (kh == 0) {
        const float* xp = xz + (size_t)(r0 + r) * T_ * G4_ + j0 + j;
        cz0 = __ldcs(xp);
        cz1 = __ldcs(xp + 256);
        cz2 = __ldcs(xp + 512);
        cz3 = __ldcs(xp + 768);
    }
    __syncthreads();

    const float* hrow_t = hs + (size_t)r * HROW + kh * 128;
    const ulonglong2* up_t = Us2 + (size_t)(kh * 128) * JL2 + j;

    for (int t = 0; t < T_; ++t) {
        // Load h(t-1) tile [8 x 256] from L2-hot hseq (skip at t=0: hs pre-zeroed)
        if (t > 0) {
#pragma unroll
            for (int i = 0; i < 2; i++) {
                int e = tid + i * 256;
                int rr = e >> 6, cc = (e & 63) * 4;
                float4 v = __ldcg((const float4*)&hseq[((size_t)(r0 + rr) * T_ + (t - 1)) * H_ + cc]);
                *(float4*)&hs[rr * HROW + cc] = v;
            }
        }
        // Prefetch next step's gate pre-activations (hidden behind FMA loop)
        float nz0 = 0.f, nz1 = 0.f, nz2 = 0.f, nz3 = 0.f;
        if (kh == 0) {
            int tn = (t + 1 < T_) ? t + 1 : t;
            const float* xp = xz + ((size_t)(r0 + r) * T_ + tn) * G4_ + j0 + j;
            nz0 = __ldcs(xp);
            nz1 = __ldcs(xp + 256);
            nz2 = __ldcs(xp + 512);
            nz3 = __ldcs(xp + 768);
        }
        __syncthreads();

        // 4 accumulator chains (A/B x 2) over this thread's 128-k half
        unsigned long long aA0 = (kh == 0) ? f2pack(cz0, cz1) : 0ULL;
        unsigned long long aB0 = (kh == 0) ? f2pack(cz2, cz3) : 0ULL;
        unsigned long long aA1 = 0ULL, aB1 = 0ULL;
#pragma unroll 4
        for (int k4 = 0; k4 < 32; k4++) {
            float4 h4 = *(const float4*)&hrow_t[k4 * 4];
            {
                unsigned long long hh = f2pack(h4.x, h4.x);
                ulonglong2 u = up_t[(size_t)(k4 * 4 + 0) * JL2];
                aA0 = f2fma(hh, u.x, aA0); aB0 = f2fma(hh, u.y, aB0);
            }
            {
                unsigned long long hh = f2pack(h4.y, h4.y);
                ulonglong2 u = up_t[(size_t)(k4 * 4 + 1) * JL2];
                aA1 = f2fma(hh, u.x, aA1); aB1 = f2fma(hh, u.y, aB1);
            }
            {
                unsigned long long hh = f2pack(h4.z, h4.z);
                ulonglong2 u = up_t[(size_t)(k4 * 4 + 2) * JL2];
                aA0 = f2fma(hh, u.x, aA0); aB0 = f2fma(hh, u.y, aB0);
            }
            {
                unsigned long long hh = f2pack(h4.w, h4.w);
                ulonglong2 u = up_t[(size_t)(k4 * 4 + 3) * JL2];
                aA1 = f2fma(hh, u.x, aA1); aB1 = f2fma(hh, u.y, aB1);
            }
        }
        unsigned long long accA = f2add(aA0, aA1);
        unsigned long long accB = f2add(aB0, aB1);
        if (kh == 1) comb[cell] = make_ulonglong2(accA, accB);
        __syncthreads();

        if (kh == 0) {
            ulonglong2 p = comb[cell];
            accA = f2add(accA, p.x);
            accB = f2add(accB, p.y);
            float azi, azf, azg, azo;
            f2unpack(accA, azi, azf);
            f2unpack(accB, azg, azo);
            float ig = sig_f(azi);
            float fg = sig_f(azf);
            float gg = tanh_f(azg);
            float og = sig_f(azo);
            c = fg * c + ig * gg;
            float h = og * tanh_f(c);
            hseq[((size_t)(r0 + r) * T_ + t) * H_ + j0 + j] = h;   // default: L2-cached
        }
        cz0 = nz0; cz1 = nz1; cz2 = nz2; cz3 = nz3;
        gsync(grp, phase);   // hseq[t] visible group-wide before t+1 reads it
    }
}

// ---------------- LayerNorm over last dim (256), one warp per row ----------------
__global__ __launch_bounds__(256) void ln_kernel(
    const float* __restrict__ X, const float* __restrict__ gamma,
    const float* __restrict__ beta, float* __restrict__ out)
{
    int w = threadIdx.x >> 5, lane = threadIdx.x & 31;
    size_t row = (size_t)blockIdx.x * 8 + w;
    const float* x = X + row * 256;
    float4 v0 = *(const float4*)&x[lane * 4];
    float4 v1 = *(const float4*)&x[128 + lane * 4];
    float s = v0.x + v0.y + v0.z + v0.w + v1.x + v1.y + v1.z + v1.w;
    float q = v0.x * v0.x + v0.y * v0.y + v0.z * v0.z + v0.w * v0.w
            + v1.x * v1.x + v1.y * v1.y + v1.z * v1.z + v1.w * v1.w;
#pragma unroll
    for (int o = 16; o > 0; o >>= 1) {
        s += __shfl_xor_sync(0xFFFFFFFFu, s, o);
        q += __shfl_xor_sync(0xFFFFFFFFu, q, o);
    }
    float mu = s * (1.f / 256.f);
    float var = q * (1.f / 256.f) - mu * mu;
    float rstd = rsqrtf(var + 1e-3f);
    float4 g0 = *(const float4*)&gamma[lane * 4];
    float4 g1 = *(const float4*)&gamma[128 + lane * 4];
    float4 e0 = *(const float4*)&beta[lane * 4];
    float4 e1 = *(const float4*)&beta[128 + lane * 4];
    float4 o0, o1;
    o0.x = (v0.x - mu) * rstd * g0.x + e0.x;
    o0.y = (v0.y - mu) * rstd * g0.y + e0.y;
    o0.z = (v0.z - mu) * rstd * g0.z + e0.z;
    o0.w = (v0.w - mu) * rstd * g0.w + e0.w;
    o1.x = (v1.x - mu) * rstd * g1.x + e1.x;
    o1.y = (v1.y - mu) * rstd * g1.y + e1.y;
    o1.z = (v1.z - mu) * rstd * g1.z + e1.z;
    o1.w = (v1.w - mu) * rstd * g1.w + e1.w;
    float* op = out + row * 256;
    *(float4*)&op[lane * 4] = o0;
    *(float4*)&op[128 + lane * 4] = o1;
}

// ---------------- entry point ----------------
extern "C" void kernel_launch(void* const* d_in, const int* in_sizes, int n_in,
                              void* d_out, int out_size)
{
    const float* x  = (const float*)d_in[0];
    const float* W0 = (const float*)d_in[1];
    const float* U0 = (const float*)d_in[2];
    const float* b0 = (const float*)d_in[3];
    const float* W1 = (const float*)d_in[4];
    const float* U1 = (const float*)d_in[5];
    const float* b1 = (const float*)d_in[6];
    const float* Wd = (const float*)d_in[7];
    const float* bd = (const float*)d_in[8];
    const float* ga = (const float*)d_in[9];
    const float* be = (const float*)d_in[10];
    float* out = (float*)d_out;

    float *xz, *hseq;
    cudaGetSymbolAddress((void**)&xz, g_xz);
    cudaGetSymbolAddress((void**)&hseq, g_hseq);
    cudaFuncSetAttribute(lstm_rec, cudaFuncAttributeMaxDynamicSharedMemorySize, REC_SMEM);

    // Layer 0
    gemm_bias<false><<<dim3(8, 512), 256>>>(x, W0, b0, xz, G4_);
    lstm_rec<<<256, 256, REC_SMEM>>>(xz, U0, hseq);
    // Layer 1
    gemm_bias<false><<<dim3(8, 512), 256>>>(hseq, W1, b1, xz, G4_);
    lstm_rec<<<256, 256, REC_SMEM>>>(xz, U1, hseq);
    // Dense + tanh (into g_xz scratch), then LayerNorm
    gemm_bias<true><<<dim3(2, 512), 256>>>(hseq, Wd, bd, xz, H_);
    ln_kernel<<<8192, 256>>>(xz, ga, be, out);
}